// round 13
// baseline (speedup 1.0000x reference)
#include <cuda_runtime.h>

// PhonologicalLoopMemory — minimal-traffic kernel, plain 256-bit accesses.
//   out[b] = concat(recent[0..3], rehearsal), segment = 32768 f32.
//   recent[0] = rehearsal = features[b]   (buf[old_pos] just set -> undecayed)
//   recent[j] = valid_j ? 0.9 * feature_buffer[b, (pos[b]-j) & 63] : 0, j=1..3
//   valid_j = buffer_filled[b] || (j <= pos[b])
//
// Traffic at floor (72 MiB). 256-bit ld/st (v4.b64) halves instruction and
// L1tex-wavefront count per byte vs float4; no eviction modifier (both
// policies measured neutral). j=0 blocks fan features out to segs 0 and 4.

#define SEG_U    4096   // segment in 32B units (131072 B / 32)
#define BUF_LEN  64
#define NSEG     5
#define UNROLL   4      // 4 x 32B = 128 B per thread
#define TPB      256

typedef unsigned long long u64;
union V32 { struct { u64 a, b, c, d; } u; float f[8]; };

__device__ __forceinline__ void ld256(const void* p, V32& v) {
    asm volatile("ld.global.v4.b64 {%0,%1,%2,%3}, [%4];"
                 : "=l"(v.u.a), "=l"(v.u.b), "=l"(v.u.c), "=l"(v.u.d) : "l"(p));
}
__device__ __forceinline__ void st256(void* p, const V32& v) {
    asm volatile("st.global.v4.b64 [%0], {%1,%2,%3,%4};"
                 :: "l"(p), "l"(v.u.a), "l"(v.u.b), "l"(v.u.c), "l"(v.u.d)
                 : "memory");
}

__global__ __launch_bounds__(TPB) void phono_kernel(
    const char* __restrict__ feat,            // [B] segments of 128 KB
    const char* __restrict__ fbuf,            // [B, 64] segments of 128 KB
    const int*  __restrict__ cur_pos,         // [B]
    const int*  __restrict__ filled,          // [B] int32 (bool upcast)
    char* __restrict__ out)                   // [B, 5] segments of 128 KB
{
    const int by = blockIdx.y;                // b*4 + j, j in 0..3 (j==0 covers segs 0 and 4)
    const int b  = by >> 2;
    const int j  = by & 3;
    const size_t base = ((size_t)blockIdx.x * (TPB * UNROLL) + threadIdx.x) * 32;  // bytes

    V32 v[UNROLL];
    char* dst0 = out + ((size_t)b * NSEG + j) * (SEG_U * 32) + base;

    if (j == 0) {
        // features -> recent[0] AND rehearsal (seg 4): one read, two writes.
        const char* src = feat + (size_t)b * (SEG_U * 32) + base;
        #pragma unroll
        for (int k = 0; k < UNROLL; k++) ld256(src + k * (TPB * 32), v[k]);

        char* dst4 = out + ((size_t)b * NSEG + 4) * (SEG_U * 32) + base;
        #pragma unroll
        for (int k = 0; k < UNROLL; k++) st256(dst0 + k * (TPB * 32), v[k]);
        #pragma unroll
        for (int k = 0; k < UNROLL; k++) st256(dst4 + k * (TPB * 32), v[k]);
        return;
    }

    const int p = cur_pos[b];
    const bool valid = (filled[b] != 0) || (j <= p);
    if (valid) {
        const int slot = (p - j + BUF_LEN) & (BUF_LEN - 1);
        const char* src = fbuf + ((size_t)b * BUF_LEN + slot) * (SEG_U * 32) + base;
        #pragma unroll
        for (int k = 0; k < UNROLL; k++) ld256(src + k * (TPB * 32), v[k]);
        #pragma unroll
        for (int k = 0; k < UNROLL; k++)
            #pragma unroll
            for (int e = 0; e < 8; e++) v[k].f[e] *= 0.9f;
    } else {
        #pragma unroll
        for (int k = 0; k < UNROLL; k++)
            #pragma unroll
            for (int e = 0; e < 8; e++) v[k].f[e] = 0.f;
    }
    #pragma unroll
    for (int k = 0; k < UNROLL; k++) st256(dst0 + k * (TPB * 32), v[k]);
}

extern "C" void kernel_launch(void* const* d_in, const int* in_sizes, int n_in,
                              void* d_out, int out_size)
{
    const char* feat   = (const char*)d_in[0];
    const char* fbuf   = (const char*)d_in[1];
    const int*  pos    = (const int*)d_in[2];
    const int*  filled = (const int*)d_in[3];
    char*       out    = (char*)d_out;

    const int batch = in_sizes[2];                    // 64
    dim3 block(TPB);
    dim3 grid(SEG_U / (TPB * UNROLL), batch * 4);     // (4, 256) = 1024 blocks
    phono_kernel<<<grid, block>>>(feat, fbuf, pos, filled, out);
}